// round 1
// baseline (speedup 1.0000x reference)
#include <cuda_runtime.h>
#include <cuda_bf16.h>
#include <cstdint>

// ---------------------------------------------------------------------------
// FiSHAttention: B=8, N=1024, dim=p=768, HEAD_DIM=64, K_GLOBAL=4, H_eff=12
//
// Pipeline:
//   1) Y   = x @ Wqkv[0:512].T          (q|k parts only; v-slot of qkv unused)
//   2) V   = x @ Wv.T                   (B,N,768) ; head h slice = cols h*64..
//   3) S4  = 0.125 * qg @ kg.T          per (b,k): 32 batched 1024x1024x64 GEMMs
//   4) attention: per (b,h,i-block): l = sum_k mix[h,k]*S4[b,k], online softmax,
//      ctx = attn @ V_h   (flash-style, poly-exp on FMA pipe)
//   5) out = ctx @ Wproj.T + b_proj
// ---------------------------------------------------------------------------

#define B_SZ   8
#define N_SEQ  1024
#define DIM    768
#define KG     4
#define HD     64
#define HEFF   12

// __device__ scratch (static: allocation-free per harness rules)
__device__ float g_Y  [B_SZ * N_SEQ * 512];             //  16 MB  (q|k)
__device__ float g_V  [B_SZ * N_SEQ * DIM];             //  24 MB
__device__ float g_ctx[B_SZ * N_SEQ * DIM];             //  24 MB
__device__ float g_S4 [(size_t)B_SZ * KG * N_SEQ * N_SEQ]; // 128 MB

// ---------------------------------------------------------------------------
// Fast exp on the FMA pipe (avoids MUFU bottleneck: 100M exps in softmax).
// exp(x) = 2^(x*log2e); round-to-nearest split via the 1.5*2^23 trick,
// degree-5 Taylor for 2^f on [-0.5,0.5] (rel err ~2.4e-6), exponent add.
// ---------------------------------------------------------------------------
__device__ __forceinline__ float fast_exp(float x) {
    x = fmaxf(x, -80.0f);                              // avoid exp underflow path
    const float L2E = 1.4426950408889634f;
    float t  = fmaf(x, L2E, 12582912.0f);              // 1.5*2^23 magic round
    float nf = t - 12582912.0f;
    int   ni = __float_as_int(t) - 0x4B400000;
    float f  = fmaf(x, L2E, -nf);
    f = fmaf(x, 1.9259629911266175e-8f, f);            // log2e low bits
    float p;
    p = 1.33335581e-3f;
    p = fmaf(p, f, 9.61812910e-3f);
    p = fmaf(p, f, 5.55041087e-2f);
    p = fmaf(p, f, 2.40226507e-1f);
    p = fmaf(p, f, 6.93147181e-1f);
    p = fmaf(p, f, 1.0f);
    return __int_as_float(__float_as_int(p) + (ni << 23));
}

// ---------------------------------------------------------------------------
// Generic TN SGEMM: C[M,N] = alpha * A[M,K] @ B[N,K]^T (+ bias), row-major.
// 128x128 tile, BK=8, 8x8 per thread, 256 threads. Batched via blockIdx.z
// with two-level (outer,inner) strides so the 32 logits GEMMs map cleanly.
// All problem dims here are multiples of the tile sizes -> no bounds checks.
// ---------------------------------------------------------------------------
__global__ __launch_bounds__(256) void sgemm_tn(
    const float* __restrict__ A, const float* __restrict__ B,
    float* __restrict__ C, const float* __restrict__ bias,
    int M, int N, int K, int lda, int ldb, int ldc, float alpha,
    long sAo, long sAi, long sBo, long sBi, long sC, int innerMod)
{
    int z = blockIdx.z;
    {
        int outer = z / innerMod;
        int inner = z - outer * innerMod;
        A += (long)outer * sAo + (long)inner * sAi;
        B += (long)outer * sBo + (long)inner * sBi;
        C += (long)z * sC;
    }

    __shared__ float As[8][128];
    __shared__ float Bs[8][128];

    const int tid  = threadIdx.x;
    const int row0 = blockIdx.y * 128;
    const int col0 = blockIdx.x * 128;

    const int la_r = tid >> 1;          // 0..127
    const int la_c = (tid & 1) << 2;    // 0 or 4
    const float* Aptr = A + (long)(row0 + la_r) * lda + la_c;
    const float* Bptr = B + (long)(col0 + la_r) * ldb + la_c;

    const int ty = tid >> 4;            // 0..15 -> rows ty*8..
    const int tx = tid & 15;            // 0..15 -> cols tx*8..

    float acc[8][8];
    #pragma unroll
    for (int i = 0; i < 8; i++)
        #pragma unroll
        for (int j = 0; j < 8; j++) acc[i][j] = 0.0f;

    for (int k0 = 0; k0 < K; k0 += 8) {
        float4 a4 = *(const float4*)(Aptr + k0);
        float4 b4 = *(const float4*)(Bptr + k0);
        As[la_c + 0][la_r] = a4.x; As[la_c + 1][la_r] = a4.y;
        As[la_c + 2][la_r] = a4.z; As[la_c + 3][la_r] = a4.w;
        Bs[la_c + 0][la_r] = b4.x; Bs[la_c + 1][la_r] = b4.y;
        Bs[la_c + 2][la_r] = b4.z; Bs[la_c + 3][la_r] = b4.w;
        __syncthreads();

        #pragma unroll
        for (int kk = 0; kk < 8; kk++) {
            float ra[8], rb[8];
            *(float4*)(ra)     = *(const float4*)&As[kk][ty * 8];
            *(float4*)(ra + 4) = *(const float4*)&As[kk][ty * 8 + 4];
            *(float4*)(rb)     = *(const float4*)&Bs[kk][tx * 8];
            *(float4*)(rb + 4) = *(const float4*)&Bs[kk][tx * 8 + 4];
            #pragma unroll
            for (int i = 0; i < 8; i++)
                #pragma unroll
                for (int j = 0; j < 8; j++)
                    acc[i][j] = fmaf(ra[i], rb[j], acc[i][j]);
        }
        __syncthreads();
    }

    #pragma unroll
    for (int i = 0; i < 8; i++) {
        long r = row0 + ty * 8 + i;
        #pragma unroll
        for (int j = 0; j < 8; j += 4) {
            int c = col0 + tx * 8 + j;
            float4 o;
            o.x = alpha * acc[i][j + 0];
            o.y = alpha * acc[i][j + 1];
            o.z = alpha * acc[i][j + 2];
            o.w = alpha * acc[i][j + 3];
            if (bias) {
                o.x += bias[c + 0]; o.y += bias[c + 1];
                o.z += bias[c + 2]; o.w += bias[c + 3];
            }
            *(float4*)&C[r * ldc + c] = o;
        }
    }
}

// ---------------------------------------------------------------------------
// Fused attention. Grid (16, 12, 8) = (i-block, head, batch). 256 threads.
// BR=64 query rows per CTA, BC=64 key cols per tile, 16 tiles over N=1024.
// Thread (rgrp = tid>>4, dseg = tid&15) owns 4 rows x 4 dims of the output
// accumulator -> one smem V float4 read feeds 16 FMAs.
// ---------------------------------------------------------------------------
#define BR 64
#define BC 64

__global__ __launch_bounds__(256) void attn_kernel(
    const float* __restrict__ S4, const float* __restrict__ V,
    const float* __restrict__ mixl, float* __restrict__ ctx)
{
    const int ib = blockIdx.x;   // 0..15
    const int h  = blockIdx.y;   // 0..11
    const int b  = blockIdx.z;   // 0..7

    __shared__ float sP[BR][BC];      // logits -> probs (16 KB)
    __shared__ float sV[BC][HD];      // V tile (16 KB)
    __shared__ float sM[BR], sL[BR], sC[BR];
    __shared__ float sMix[4];

    const int tid = threadIdx.x;

    if (tid < 4) {  // softmax of mix_logits[h, 0:4] (computed redundantly x4)
        float l0 = mixl[h * 4 + 0], l1 = mixl[h * 4 + 1];
        float l2 = mixl[h * 4 + 2], l3 = mixl[h * 4 + 3];
        float m  = fmaxf(fmaxf(l0, l1), fmaxf(l2, l3));
        float e0 = fast_exp(l0 - m), e1 = fast_exp(l1 - m);
        float e2 = fast_exp(l2 - m), e3 = fast_exp(l3 - m);
        float s  = e0 + e1 + e2 + e3;
        float mine = (tid == 0) ? e0 : (tid == 1) ? e1 : (tid == 2) ? e2 : e3;
        sMix[tid] = mine / s;
    }
    if (tid < BR) { sM[tid] = -1e30f; sL[tid] = 0.0f; }
    __syncthreads();

    const float mx0 = sMix[0], mx1 = sMix[1], mx2 = sMix[2], mx3 = sMix[3];

    const int i0   = ib * BR;
    const int rgrp = tid >> 4;     // 0..15 -> rows rgrp*4 .. rgrp*4+3
    const int dseg = tid & 15;     // 0..15 -> dims dseg*4 .. dseg*4+3

    float acc[4][4];
    #pragma unroll
    for (int i = 0; i < 4; i++)
        #pragma unroll
        for (int j = 0; j < 4; j++) acc[i][j] = 0.0f;

    const float* S4b = S4 + (long)b * KG * N_SEQ * N_SEQ;
    const float* Vb  = V + (long)b * N_SEQ * DIM + h * HD;
    const long   PL  = (long)N_SEQ * N_SEQ;   // plane stride

    for (int j0 = 0; j0 < N_SEQ; j0 += BC) {
        // -- phase 1: load V tile + combine 4 logit planes into sP -----------
        #pragma unroll
        for (int e = tid; e < BC * (HD / 4); e += 256) {     // 1024 float4
            int j = e >> 4, dq = (e & 15) << 2;
            *(float4*)&sV[j][dq] = *(const float4*)&Vb[(long)(j0 + j) * DIM + dq];
        }
        #pragma unroll
        for (int e = tid; e < BR * BC; e += 256) {
            int i = e >> 6, j = e & 63;
            long base = (long)(i0 + i) * N_SEQ + j0 + j;
            float l = mx0 * S4b[base]
                    + mx1 * S4b[base + PL]
                    + mx2 * S4b[base + 2 * PL]
                    + mx3 * S4b[base + 3 * PL];
            sP[i][j] = l;
        }
        __syncthreads();

        // -- phase 2: online softmax update (4 threads per row) --------------
        {
            int row = tid >> 2, q = tid & 3;
            float lv[16];
            float lm = -1e30f;
            #pragma unroll
            for (int jj = 0; jj < 16; jj++) {
                float l = sP[row][q * 16 + jj];
                lv[jj] = l; lm = fmaxf(lm, l);
            }
            lm = fmaxf(lm, __shfl_xor_sync(0xffffffffu, lm, 1));
            lm = fmaxf(lm, __shfl_xor_sync(0xffffffffu, lm, 2));
            float mold = sM[row];
            float mnew = fmaxf(mold, lm);
            float ssum = 0.0f;
            #pragma unroll
            for (int jj = 0; jj < 16; jj++) {
                float p = fast_exp(lv[jj] - mnew);
                sP[row][q * 16 + jj] = p;
                ssum += p;
            }
            ssum += __shfl_xor_sync(0xffffffffu, ssum, 1);
            ssum += __shfl_xor_sync(0xffffffffu, ssum, 2);
            if (q == 0) {
                float c = fast_exp(mold - mnew);
                sC[row] = c;
                sL[row] = sL[row] * c + ssum;
                sM[row] = mnew;
            }
        }
        __syncthreads();

        // -- phase 3: rescale + accumulate P @ V -----------------------------
        #pragma unroll
        for (int rr = 0; rr < 4; rr++) {
            float c = sC[rgrp * 4 + rr];
            acc[rr][0] *= c; acc[rr][1] *= c; acc[rr][2] *= c; acc[rr][3] *= c;
        }
        #pragma unroll 8
        for (int j = 0; j < BC; j++) {
            float4 v4 = *(const float4*)&sV[j][dseg * 4];
            #pragma unroll
            for (int rr = 0; rr < 4; rr++) {
                float p = sP[rgrp * 4 + rr][j];   // broadcast across 16 lanes
                acc[rr][0] = fmaf(p, v4.x, acc[rr][0]);
                acc[rr][1] = fmaf(p, v4.y, acc[rr][1]);
                acc[rr][2] = fmaf(p, v4.z, acc[rr][2]);
                acc[rr][3] = fmaf(p, v4.w, acc[rr][3]);
            }
        }
        __syncthreads();
    }

    // -- epilogue: normalize, write ctx[b, i, h*64+d] -------------------------
    #pragma unroll
    for (int rr = 0; rr < 4; rr++) {
        int r = rgrp * 4 + rr;
        float inv = 1.0f / sL[r];
        float4 o;
        o.x = acc[rr][0] * inv; o.y = acc[rr][1] * inv;
        o.z = acc[rr][2] * inv; o.w = acc[rr][3] * inv;
        *(float4*)&ctx[((long)b * N_SEQ + i0 + r) * DIM + h * HD + dseg * 4] = o;
    }
}

// ---------------------------------------------------------------------------
// kernel_launch: inputs per metadata order:
//   0 x, 1 W_qkv, 2 W_v, 3 W_proj, 4 b_proj, 5 mix_logits, 6 p (ignored, =768)
// Output: float32 (8,1024,768)
// ---------------------------------------------------------------------------
extern "C" void kernel_launch(void* const* d_in, const int* in_sizes, int n_in,
                              void* d_out, int out_size)
{
    const float* x      = (const float*)d_in[0];
    const float* W_qkv  = (const float*)d_in[1];
    const float* W_v    = (const float*)d_in[2];
    const float* W_proj = (const float*)d_in[3];
    const float* b_proj = (const float*)d_in[4];
    const float* mixl   = (const float*)d_in[5];
    float* out = (float*)d_out;

    float *pY, *pV, *pCtx, *pS4;
    cudaGetSymbolAddress((void**)&pY,   g_Y);
    cudaGetSymbolAddress((void**)&pV,   g_V);
    cudaGetSymbolAddress((void**)&pCtx, g_ctx);
    cudaGetSymbolAddress((void**)&pS4,  g_S4);

    const int M = B_SZ * N_SEQ;   // 8192
    dim3 blk(256);

    // 1) Y = x @ W_qkv[0:512].T   (q|k slots only)
    sgemm_tn<<<dim3(512 / 128, M / 128, 1), blk>>>(
        x, W_qkv, pY, nullptr, M, 512, DIM, DIM, DIM, 512, 1.0f,
        0, 0, 0, 0, 0, 1);

    // 2) V = x @ W_v.T
    sgemm_tn<<<dim3(DIM / 128, M / 128, 1), blk>>>(
        x, W_v, pV, nullptr, M, DIM, DIM, DIM, DIM, DIM, 1.0f,
        0, 0, 0, 0, 0, 1);

    // 3) S4[b,k] = 0.125 * q_k @ k_k.T   (32 batched 1024x1024x64 GEMMs)
    //    z = b*4 + k ; A off = b*(1024*512) + k*64 ; B off = same + 256 cols
    sgemm_tn<<<dim3(N_SEQ / 128, N_SEQ / 128, B_SZ * KG), blk>>>(
        pY, pY + 256, pS4, nullptr, N_SEQ, N_SEQ, HD, 512, 512, N_SEQ, 0.125f,
        (long)N_SEQ * 512, 64, (long)N_SEQ * 512, 64, (long)N_SEQ * N_SEQ, KG);

    // 4) fused mix + softmax + PV
    attn_kernel<<<dim3(N_SEQ / BR, HEFF, B_SZ), blk>>>(pS4, pV, mixl, pCtx);

    // 5) out = ctx @ W_proj.T + b_proj
    sgemm_tn<<<dim3(DIM / 128, M / 128, 1), blk>>>(
        pCtx, W_proj, out, b_proj, M, DIM, DIM, DIM, DIM, DIM, 1.0f,
        0, 0, 0, 0, 0, 1);
}

// round 2
// speedup vs baseline: 1.0305x; 1.0305x over previous
#include <cuda_runtime.h>
#include <cuda_bf16.h>
#include <cstdint>

// ---------------------------------------------------------------------------
// FiSHAttention: B=8, N=1024, dim=p=768, HEAD_DIM=64, K_GLOBAL=4, H_eff=12
//
// Pipeline:
//   1) Y   = x @ Wqkv[0:512].T          (q|k parts only)
//   2) V   = x @ Wv.T
//   3) S4  = 0.125 * qg @ kg.T          per (b,k): 32 batched 1024x1024x64
//   4) attention: fused combine(mix)+softmax+PV, P transposed in smem
//   5) out = ctx @ Wproj.T + b_proj
// ---------------------------------------------------------------------------

#define B_SZ   8
#define N_SEQ  1024
#define DIM    768
#define KG     4
#define HD     64
#define HEFF   12

__device__ float g_Y  [B_SZ * N_SEQ * 512];
__device__ float g_V  [B_SZ * N_SEQ * DIM];
__device__ float g_ctx[B_SZ * N_SEQ * DIM];
__device__ float g_S4 [(size_t)B_SZ * KG * N_SEQ * N_SEQ];

// ---------------------------------------------------------------------------
// Fast exp on the FMA pipe (MUFU would bottleneck 100M softmax exps).
// ---------------------------------------------------------------------------
__device__ __forceinline__ float fast_exp(float x) {
    x = fmaxf(x, -80.0f);
    const float L2E = 1.4426950408889634f;
    float t  = fmaf(x, L2E, 12582912.0f);
    float nf = t - 12582912.0f;
    int   ni = __float_as_int(t) - 0x4B400000;
    float f  = fmaf(x, L2E, -nf);
    f = fmaf(x, 1.9259629911266175e-8f, f);
    float p;
    p = 1.33335581e-3f;
    p = fmaf(p, f, 9.61812910e-3f);
    p = fmaf(p, f, 5.55041087e-2f);
    p = fmaf(p, f, 2.40226507e-1f);
    p = fmaf(p, f, 6.93147181e-1f);
    p = fmaf(p, f, 1.0f);
    return __int_as_float(__float_as_int(p) + (ni << 23));
}

// ---------------------------------------------------------------------------
// TN SGEMM, 128x128 tile, BK=8, 8x8/thread, 256 thr, DOUBLE-BUFFERED smem.
// C[M,N] = alpha * A[M,K] @ B[N,K]^T (+bias). Batched via blockIdx.z.
// ---------------------------------------------------------------------------
__global__ __launch_bounds__(256) void sgemm_tn(
    const float* __restrict__ A, const float* __restrict__ B,
    float* __restrict__ C, const float* __restrict__ bias,
    int M, int N, int K, int lda, int ldb, int ldc, float alpha,
    long sAo, long sAi, long sBo, long sBi, long sC, int innerMod)
{
    int z = blockIdx.z;
    {
        int outer = z / innerMod;
        int inner = z - outer * innerMod;
        A += (long)outer * sAo + (long)inner * sAi;
        B += (long)outer * sBo + (long)inner * sBi;
        C += (long)z * sC;
    }

    __shared__ float As[2][8][128];
    __shared__ float Bs[2][8][128];

    const int tid  = threadIdx.x;
    const int row0 = blockIdx.y * 128;
    const int col0 = blockIdx.x * 128;

    const int la_r = tid >> 1;
    const int la_c = (tid & 1) << 2;
    const float* Aptr = A + (long)(row0 + la_r) * lda + la_c;
    const float* Bptr = B + (long)(col0 + la_r) * ldb + la_c;

    const int ty = tid >> 4;
    const int tx = tid & 15;

    float acc[8][8];
    #pragma unroll
    for (int i = 0; i < 8; i++)
        #pragma unroll
        for (int j = 0; j < 8; j++) acc[i][j] = 0.0f;

    // prolog: tile 0 -> buffer 0
    {
        float4 a4 = *(const float4*)(Aptr);
        float4 b4 = *(const float4*)(Bptr);
        As[0][la_c + 0][la_r] = a4.x; As[0][la_c + 1][la_r] = a4.y;
        As[0][la_c + 2][la_r] = a4.z; As[0][la_c + 3][la_r] = a4.w;
        Bs[0][la_c + 0][la_r] = b4.x; Bs[0][la_c + 1][la_r] = b4.y;
        Bs[0][la_c + 2][la_r] = b4.z; Bs[0][la_c + 3][la_r] = b4.w;
    }
    __syncthreads();

    const int nT = K >> 3;
    for (int t = 0; t < nT; t++) {
        const int cur = t & 1;
        float4 na, nb;
        const bool more = (t + 1 < nT);
        if (more) {
            na = *(const float4*)(Aptr + (t + 1) * 8);
            nb = *(const float4*)(Bptr + (t + 1) * 8);
        }

        #pragma unroll
        for (int kk = 0; kk < 8; kk++) {
            float ra[8], rb[8];
            *(float4*)(ra)     = *(const float4*)&As[cur][kk][ty * 8];
            *(float4*)(ra + 4) = *(const float4*)&As[cur][kk][ty * 8 + 4];
            *(float4*)(rb)     = *(const float4*)&Bs[cur][kk][tx * 8];
            *(float4*)(rb + 4) = *(const float4*)&Bs[cur][kk][tx * 8 + 4];
            #pragma unroll
            for (int i = 0; i < 8; i++)
                #pragma unroll
                for (int j = 0; j < 8; j++)
                    acc[i][j] = fmaf(ra[i], rb[j], acc[i][j]);
        }

        if (more) {
            const int nx = cur ^ 1;
            As[nx][la_c + 0][la_r] = na.x; As[nx][la_c + 1][la_r] = na.y;
            As[nx][la_c + 2][la_r] = na.z; As[nx][la_c + 3][la_r] = na.w;
            Bs[nx][la_c + 0][la_r] = nb.x; Bs[nx][la_c + 1][la_r] = nb.y;
            Bs[nx][la_c + 2][la_r] = nb.z; Bs[nx][la_c + 3][la_r] = nb.w;
        }
        __syncthreads();
    }

    #pragma unroll
    for (int i = 0; i < 8; i++) {
        long r = row0 + ty * 8 + i;
        #pragma unroll
        for (int j = 0; j < 8; j += 4) {
            int c = col0 + tx * 8 + j;
            float4 o;
            o.x = alpha * acc[i][j + 0];
            o.y = alpha * acc[i][j + 1];
            o.z = alpha * acc[i][j + 2];
            o.w = alpha * acc[i][j + 3];
            if (bias) {
                o.x += bias[c + 0]; o.y += bias[c + 1];
                o.z += bias[c + 2]; o.w += bias[c + 3];
            }
            *(float4*)&C[r * ldc + c] = o;
        }
    }
}

// ---------------------------------------------------------------------------
// Fused attention v2. Grid (16, 12, 8), 256 threads. BR=64 rows, BC=64 cols.
// Phase A: 4 threads/row combine 4 logit planes + online softmax in registers,
//          write probs TRANSPOSED to sPt[j][row] (stride 68).
// Phase B: thread (rgrp,dseg) owns 4 rows x 4 dims; per j: 1 LDS.128 P
//          (broadcast) + 1 LDS.128 V feed 16 FMAs.
// ---------------------------------------------------------------------------
#define BR 64
#define BC 64
#define PSTR 68   // sPt row stride (floats): 64+4 keeps 16B align, kills conflicts

__global__ __launch_bounds__(256) void attn_kernel(
    const float* __restrict__ S4, const float* __restrict__ V,
    const float* __restrict__ mixl, float* __restrict__ ctx)
{
    const int ib = blockIdx.x;
    const int h  = blockIdx.y;
    const int b  = blockIdx.z;

    __shared__ float sPt[BC][PSTR];      // transposed probs (~17.4 KB)
    __shared__ float sV[BC][HD];         // V tile (16 KB)
    __shared__ float sM[BR], sL[BR], sC[BR];
    __shared__ float sMix[4];

    const int tid = threadIdx.x;

    if (tid < 4) {
        float l0 = mixl[h * 4 + 0], l1 = mixl[h * 4 + 1];
        float l2 = mixl[h * 4 + 2], l3 = mixl[h * 4 + 3];
        float m  = fmaxf(fmaxf(l0, l1), fmaxf(l2, l3));
        float e0 = fast_exp(l0 - m), e1 = fast_exp(l1 - m);
        float e2 = fast_exp(l2 - m), e3 = fast_exp(l3 - m);
        float s  = e0 + e1 + e2 + e3;
        float mine = (tid == 0) ? e0 : (tid == 1) ? e1 : (tid == 2) ? e2 : e3;
        sMix[tid] = mine / s;
    }
    if (tid < BR) { sM[tid] = -1e30f; sL[tid] = 0.0f; }
    __syncthreads();

    const float mx0 = sMix[0], mx1 = sMix[1], mx2 = sMix[2], mx3 = sMix[3];

    const int i0   = ib * BR;
    const int rgrp = tid >> 4;        // 0..15 -> rows rgrp*4..+3
    const int dseg = tid & 15;        // 0..15 -> dims dseg*4..+3
    const int arow = tid >> 2;        // phase A: row 0..63
    const int aq   = tid & 3;         // phase A: quarter 0..3 (16 j each)

    float acc[4][4];
    #pragma unroll
    for (int i = 0; i < 4; i++)
        #pragma unroll
        for (int j = 0; j < 4; j++) acc[i][j] = 0.0f;

    const float* S4b = S4 + (long)b * KG * N_SEQ * N_SEQ;
    const float* Vb  = V + (long)b * N_SEQ * DIM + h * HD;
    const long   PL  = (long)N_SEQ * N_SEQ;

    for (int j0 = 0; j0 < N_SEQ; j0 += BC) {
        // ---- load V tile (all threads) --------------------------------------
        #pragma unroll
        for (int it = 0; it < 4; it++) {
            int e = tid + it * 256;
            int j = e >> 4, dq = (e & 15) << 2;
            *(float4*)&sV[j][dq] = *(const float4*)&Vb[(long)(j0 + j) * DIM + dq];
        }

        // ---- phase A: combine + online softmax, write transposed ------------
        {
            const float* base = S4b + (long)(i0 + arow) * N_SEQ + j0 + aq * 16;
            float lv[16];
            float lm = -1e30f;
            #pragma unroll
            for (int c = 0; c < 4; c++) {
                float4 a  = *(const float4*)(base + c * 4);
                float4 p1 = *(const float4*)(base + PL + c * 4);
                float4 p2 = *(const float4*)(base + 2 * PL + c * 4);
                float4 p3 = *(const float4*)(base + 3 * PL + c * 4);
                float v0 = fmaf(mx3, p3.x, fmaf(mx2, p2.x, fmaf(mx1, p1.x, mx0 * a.x)));
                float v1 = fmaf(mx3, p3.y, fmaf(mx2, p2.y, fmaf(mx1, p1.y, mx0 * a.y)));
                float v2 = fmaf(mx3, p3.z, fmaf(mx2, p2.z, fmaf(mx1, p1.z, mx0 * a.z)));
                float v3 = fmaf(mx3, p3.w, fmaf(mx2, p2.w, fmaf(mx1, p1.w, mx0 * a.w)));
                lv[c * 4 + 0] = v0; lv[c * 4 + 1] = v1;
                lv[c * 4 + 2] = v2; lv[c * 4 + 3] = v3;
                lm = fmaxf(lm, fmaxf(fmaxf(v0, v1), fmaxf(v2, v3)));
            }
            lm = fmaxf(lm, __shfl_xor_sync(0xffffffffu, lm, 1));
            lm = fmaxf(lm, __shfl_xor_sync(0xffffffffu, lm, 2));
            float mold = sM[arow];
            float mnew = fmaxf(mold, lm);
            float ssum = 0.0f;
            #pragma unroll
            for (int c = 0; c < 16; c++) {
                float p = fast_exp(lv[c] - mnew);
                sPt[aq * 16 + c][arow] = p;
                ssum += p;
            }
            ssum += __shfl_xor_sync(0xffffffffu, ssum, 1);
            ssum += __shfl_xor_sync(0xffffffffu, ssum, 2);
            if (aq == 0) {
                float cf = fast_exp(mold - mnew);
                sC[arow] = cf;
                sL[arow] = sL[arow] * cf + ssum;
                sM[arow] = mnew;
            }
        }
        __syncthreads();

        // ---- phase B: rescale + P @ V accumulate ----------------------------
        #pragma unroll
        for (int rr = 0; rr < 4; rr++) {
            float cf = sC[rgrp * 4 + rr];
            acc[rr][0] *= cf; acc[rr][1] *= cf; acc[rr][2] *= cf; acc[rr][3] *= cf;
        }
        #pragma unroll 4
        for (int j = 0; j < BC; j++) {
            float4 p4 = *(const float4*)&sPt[j][rgrp * 4];   // probs for 4 rows
            float4 v4 = *(const float4*)&sV[j][dseg * 4];    // V for 4 dims
            acc[0][0] = fmaf(p4.x, v4.x, acc[0][0]);
            acc[0][1] = fmaf(p4.x, v4.y, acc[0][1]);
            acc[0][2] = fmaf(p4.x, v4.z, acc[0][2]);
            acc[0][3] = fmaf(p4.x, v4.w, acc[0][3]);
            acc[1][0] = fmaf(p4.y, v4.x, acc[1][0]);
            acc[1][1] = fmaf(p4.y, v4.y, acc[1][1]);
            acc[1][2] = fmaf(p4.y, v4.z, acc[1][2]);
            acc[1][3] = fmaf(p4.y, v4.w, acc[1][3]);
            acc[2][0] = fmaf(p4.z, v4.x, acc[2][0]);
            acc[2][1] = fmaf(p4.z, v4.y, acc[2][1]);
            acc[2][2] = fmaf(p4.z, v4.z, acc[2][2]);
            acc[2][3] = fmaf(p4.z, v4.w, acc[2][3]);
            acc[3][0] = fmaf(p4.w, v4.x, acc[3][0]);
            acc[3][1] = fmaf(p4.w, v4.y, acc[3][1]);
            acc[3][2] = fmaf(p4.w, v4.z, acc[3][2]);
            acc[3][3] = fmaf(p4.w, v4.w, acc[3][3]);
        }
        __syncthreads();
    }

    // ---- epilogue: normalize + write ctx -----------------------------------
    #pragma unroll
    for (int rr = 0; rr < 4; rr++) {
        int r = rgrp * 4 + rr;
        float inv = 1.0f / sL[r];
        float4 o;
        o.x = acc[rr][0] * inv; o.y = acc[rr][1] * inv;
        o.z = acc[rr][2] * inv; o.w = acc[rr][3] * inv;
        *(float4*)&ctx[((long)b * N_SEQ + i0 + r) * DIM + h * HD + dseg * 4] = o;
    }
}

// ---------------------------------------------------------------------------
extern "C" void kernel_launch(void* const* d_in, const int* in_sizes, int n_in,
                              void* d_out, int out_size)
{
    const float* x      = (const float*)d_in[0];
    const float* W_qkv  = (const float*)d_in[1];
    const float* W_v    = (const float*)d_in[2];
    const float* W_proj = (const float*)d_in[3];
    const float* b_proj = (const float*)d_in[4];
    const float* mixl   = (const float*)d_in[5];
    float* out = (float*)d_out;

    float *pY, *pV, *pCtx, *pS4;
    cudaGetSymbolAddress((void**)&pY,   g_Y);
    cudaGetSymbolAddress((void**)&pV,   g_V);
    cudaGetSymbolAddress((void**)&pCtx, g_ctx);
    cudaGetSymbolAddress((void**)&pS4,  g_S4);

    const int M = B_SZ * N_SEQ;
    dim3 blk(256);

    sgemm_tn<<<dim3(512 / 128, M / 128, 1), blk>>>(
        x, W_qkv, pY, nullptr, M, 512, DIM, DIM, DIM, 512, 1.0f,
        0, 0, 0, 0, 0, 1);

    sgemm_tn<<<dim3(DIM / 128, M / 128, 1), blk>>>(
        x, W_v, pV, nullptr, M, DIM, DIM, DIM, DIM, DIM, 1.0f,
        0, 0, 0, 0, 0, 1);

    sgemm_tn<<<dim3(N_SEQ / 128, N_SEQ / 128, B_SZ * KG), blk>>>(
        pY, pY + 256, pS4, nullptr, N_SEQ, N_SEQ, HD, 512, 512, N_SEQ, 0.125f,
        (long)N_SEQ * 512, 64, (long)N_SEQ * 512, 64, (long)N_SEQ * N_SEQ, KG);

    attn_kernel<<<dim3(N_SEQ / BR, HEFF, B_SZ), blk>>>(pS4, pV, mixl, pCtx);

    sgemm_tn<<<dim3(DIM / 128, M / 128, 1), blk>>>(
        pCtx, W_proj, out, b_proj, M, DIM, DIM, DIM, DIM, DIM, 1.0f,
        0, 0, 0, 0, 0, 1);
}

// round 3
// speedup vs baseline: 1.1484x; 1.1145x over previous
#include <cuda_runtime.h>
#include <cuda_bf16.h>
#include <cstdint>

// ---------------------------------------------------------------------------
// FiSHAttention: B=8, N=1024, dim=p=768, HEAD_DIM=64, K_GLOBAL=4, H_eff=12
//   1) Y   = x @ Wqkv[0:512].T
//   2) V   = x @ Wv.T
//   3) S4  = 0.125 * qg @ kg.T   (32 batched 1024x1024x64)
//   4) attention: combine(mix)+exp (no-max softmax; logits bounded ~±2) + PV
//   5) out = ctx @ Wproj.T + b_proj
// ---------------------------------------------------------------------------

#define B_SZ   8
#define N_SEQ  1024
#define DIM    768
#define KG     4
#define HD     64
#define HEFF   12

__device__ float g_Y  [B_SZ * N_SEQ * 512];
__device__ float g_V  [B_SZ * N_SEQ * DIM];
__device__ float g_ctx[B_SZ * N_SEQ * DIM];
__device__ float g_S4 [(size_t)B_SZ * KG * N_SEQ * N_SEQ];

// exp(x) via poly (FMA pipe; MUFU would bottleneck). Used for tiny mix softmax.
__device__ __forceinline__ float fast_exp(float x) {
    x = fmaxf(x, -80.0f);
    const float L2E = 1.4426950408889634f;
    float t  = fmaf(x, L2E, 12582912.0f);
    float nf = t - 12582912.0f;
    int   ni = __float_as_int(t) - 0x4B400000;
    float f  = fmaf(x, L2E, -nf);
    f = fmaf(x, 1.9259629911266175e-8f, f);
    float p;
    p = 1.33335581e-3f;
    p = fmaf(p, f, 9.61812910e-3f);
    p = fmaf(p, f, 5.55041087e-2f);
    p = fmaf(p, f, 2.40226507e-1f);
    p = fmaf(p, f, 6.93147181e-1f);
    p = fmaf(p, f, 1.0f);
    return __int_as_float(__float_as_int(p) + (ni << 23));
}

// 2^y, y pre-scaled by log2(e). |y| small (<8) here -> no clamp needed, but
// keep a floor for safety.
__device__ __forceinline__ float fast_exp2(float y) {
    y = fmaxf(y, -100.0f);
    float t  = y + 12582912.0f;                 // round-to-nearest int
    float nf = t - 12582912.0f;
    int   ni = __float_as_int(t) - 0x4B400000;
    float f  = y - nf;                          // f in [-0.5, 0.5]
    float p;
    p = 1.33335581e-3f;
    p = fmaf(p, f, 9.61812910e-3f);
    p = fmaf(p, f, 5.55041087e-2f);
    p = fmaf(p, f, 2.40226507e-1f);
    p = fmaf(p, f, 6.93147181e-1f);
    p = fmaf(p, f, 1.0f);
    return __int_as_float(__float_as_int(p) + (ni << 23));
}

// ---------------------------------------------------------------------------
// TN SGEMM, 128x128 tile, BK=8, 8x8/thread, 256 thr, double-buffered smem.
// ---------------------------------------------------------------------------
__global__ __launch_bounds__(256) void sgemm_tn(
    const float* __restrict__ A, const float* __restrict__ B,
    float* __restrict__ C, const float* __restrict__ bias,
    int M, int N, int K, int lda, int ldb, int ldc, float alpha,
    long sAo, long sAi, long sBo, long sBi, long sC, int innerMod)
{
    int z = blockIdx.z;
    {
        int outer = z / innerMod;
        int inner = z - outer * innerMod;
        A += (long)outer * sAo + (long)inner * sAi;
        B += (long)outer * sBo + (long)inner * sBi;
        C += (long)z * sC;
    }

    __shared__ float As[2][8][128];
    __shared__ float Bs[2][8][128];

    const int tid  = threadIdx.x;
    const int row0 = blockIdx.y * 128;
    const int col0 = blockIdx.x * 128;

    const int la_r = tid >> 1;
    const int la_c = (tid & 1) << 2;
    const float* Aptr = A + (long)(row0 + la_r) * lda + la_c;
    const float* Bptr = B + (long)(col0 + la_r) * ldb + la_c;

    const int ty = tid >> 4;
    const int tx = tid & 15;

    float acc[8][8];
    #pragma unroll
    for (int i = 0; i < 8; i++)
        #pragma unroll
        for (int j = 0; j < 8; j++) acc[i][j] = 0.0f;

    {
        float4 a4 = *(const float4*)(Aptr);
        float4 b4 = *(const float4*)(Bptr);
        As[0][la_c + 0][la_r] = a4.x; As[0][la_c + 1][la_r] = a4.y;
        As[0][la_c + 2][la_r] = a4.z; As[0][la_c + 3][la_r] = a4.w;
        Bs[0][la_c + 0][la_r] = b4.x; Bs[0][la_c + 1][la_r] = b4.y;
        Bs[0][la_c + 2][la_r] = b4.z; Bs[0][la_c + 3][la_r] = b4.w;
    }
    __syncthreads();

    const int nT = K >> 3;
    for (int t = 0; t < nT; t++) {
        const int cur = t & 1;
        float4 na, nb;
        const bool more = (t + 1 < nT);
        if (more) {
            na = *(const float4*)(Aptr + (t + 1) * 8);
            nb = *(const float4*)(Bptr + (t + 1) * 8);
        }

        #pragma unroll
        for (int kk = 0; kk < 8; kk++) {
            float ra[8], rb[8];
            *(float4*)(ra)     = *(const float4*)&As[cur][kk][ty * 8];
            *(float4*)(ra + 4) = *(const float4*)&As[cur][kk][ty * 8 + 4];
            *(float4*)(rb)     = *(const float4*)&Bs[cur][kk][tx * 8];
            *(float4*)(rb + 4) = *(const float4*)&Bs[cur][kk][tx * 8 + 4];
            #pragma unroll
            for (int i = 0; i < 8; i++)
                #pragma unroll
                for (int j = 0; j < 8; j++)
                    acc[i][j] = fmaf(ra[i], rb[j], acc[i][j]);
        }

        if (more) {
            const int nx = cur ^ 1;
            As[nx][la_c + 0][la_r] = na.x; As[nx][la_c + 1][la_r] = na.y;
            As[nx][la_c + 2][la_r] = na.z; As[nx][la_c + 3][la_r] = na.w;
            Bs[nx][la_c + 0][la_r] = nb.x; Bs[nx][la_c + 1][la_r] = nb.y;
            Bs[nx][la_c + 2][la_r] = nb.z; Bs[nx][la_c + 3][la_r] = nb.w;
        }
        __syncthreads();
    }

    #pragma unroll
    for (int i = 0; i < 8; i++) {
        long r = row0 + ty * 8 + i;
        #pragma unroll
        for (int j = 0; j < 8; j += 4) {
            int c = col0 + tx * 8 + j;
            float4 o;
            o.x = alpha * acc[i][j + 0];
            o.y = alpha * acc[i][j + 1];
            o.z = alpha * acc[i][j + 2];
            o.w = alpha * acc[i][j + 3];
            if (bias) {
                o.x += bias[c + 0]; o.y += bias[c + 1];
                o.z += bias[c + 2]; o.w += bias[c + 3];
            }
            *(float4*)&C[r * ldc + c] = o;
        }
    }
}

// ---------------------------------------------------------------------------
// Fused attention v3. Grid (16, 12, 8), 256 threads. BR=64, BC=64.
// No-max softmax (bounded logits). Phase A: coalesced float4 combine + exp2,
// row-major sP (padded 68), row sums via shfl. Phase B: 4 rows x 8 dims per
// thread, split into two j-halves; per j: 4 bcast P + 2 LDS.128 V -> 32 FMA.
// ---------------------------------------------------------------------------
#define BR 64
#define BC 64
#define PSTR 68

__global__ __launch_bounds__(256) void attn_kernel(
    const float* __restrict__ S4, const float* __restrict__ V,
    const float* __restrict__ mixl, float* __restrict__ ctx)
{
    const int ib = blockIdx.x;
    const int h  = blockIdx.y;
    const int b  = blockIdx.z;

    __shared__ float sP[BR][PSTR];      // probs, row-major   (~17.4 KB)
    __shared__ float sV[BC][HD];        // V tile             (16 KB)
    __shared__ float sSum[BR];
    __shared__ float sMix[4];

    const int tid = threadIdx.x;

    if (tid < 4) {   // softmax(mix_logits[h]) * log2(e)
        float l0 = mixl[h * 4 + 0], l1 = mixl[h * 4 + 1];
        float l2 = mixl[h * 4 + 2], l3 = mixl[h * 4 + 3];
        float m  = fmaxf(fmaxf(l0, l1), fmaxf(l2, l3));
        float e0 = fast_exp(l0 - m), e1 = fast_exp(l1 - m);
        float e2 = fast_exp(l2 - m), e3 = fast_exp(l3 - m);
        float s  = e0 + e1 + e2 + e3;
        float mine = (tid == 0) ? e0 : (tid == 1) ? e1 : (tid == 2) ? e2 : e3;
        sMix[tid] = (mine / s) * 1.4426950408889634f;
    }
    if (tid < BR) sSum[tid] = 0.0f;
    __syncthreads();

    const float mx0 = sMix[0], mx1 = sMix[1], mx2 = sMix[2], mx3 = sMix[3];

    const int i0 = ib * BR;

    // phase B thread mapping: jh selects j-half, rgrp = 4 rows, dseg = 8 dims
    const int jh   = tid >> 7;          // 0 or 1
    const int rgrp = (tid >> 3) & 15;   // rows rgrp*4 .. +3
    const int dseg = tid & 7;           // dims {dseg*4..+3} U {32+dseg*4..+3}

    float acc[4][8];
    #pragma unroll
    for (int i = 0; i < 4; i++)
        #pragma unroll
        for (int j = 0; j < 8; j++) acc[i][j] = 0.0f;

    const float* S4b = S4 + (long)b * KG * N_SEQ * N_SEQ;
    const float* Vb  = V + (long)b * N_SEQ * DIM + h * HD;
    const long   PL  = (long)N_SEQ * N_SEQ;

    for (int j0 = 0; j0 < N_SEQ; j0 += BC) {
        // ---- V tile: 1024 float4, coalesced --------------------------------
        #pragma unroll
        for (int it = 0; it < 4; it++) {
            int e = it * 256 + tid;
            int j = e >> 4, dq = (e & 15) << 2;
            *(float4*)&sV[j][dq] = *(const float4*)&Vb[(long)(j0 + j) * DIM + dq];
        }

        // ---- phase A: combine 4 planes + exp2, write sP, row sums ----------
        #pragma unroll
        for (int c = 0; c < 4; c++) {
            int row  = c * 16 + (tid >> 4);
            int col  = (tid & 15) << 2;
            const float* base = S4b + (long)(i0 + row) * N_SEQ + j0 + col;
            float4 a  = *(const float4*)(base);
            float4 p1 = *(const float4*)(base + PL);
            float4 p2 = *(const float4*)(base + 2 * PL);
            float4 p3 = *(const float4*)(base + 3 * PL);
            float4 pr;
            pr.x = fast_exp2(fmaf(mx3, p3.x, fmaf(mx2, p2.x, fmaf(mx1, p1.x, mx0 * a.x))));
            pr.y = fast_exp2(fmaf(mx3, p3.y, fmaf(mx2, p2.y, fmaf(mx1, p1.y, mx0 * a.y))));
            pr.z = fast_exp2(fmaf(mx3, p3.z, fmaf(mx2, p2.z, fmaf(mx1, p1.z, mx0 * a.z))));
            pr.w = fast_exp2(fmaf(mx3, p3.w, fmaf(mx2, p2.w, fmaf(mx1, p1.w, mx0 * a.w))));
            *(float4*)&sP[row][col] = pr;

            // row-sum: reduce across the 16 lanes sharing this row
            float s = (pr.x + pr.y) + (pr.z + pr.w);
            s += __shfl_xor_sync(0xffffffffu, s, 1);
            s += __shfl_xor_sync(0xffffffffu, s, 2);
            s += __shfl_xor_sync(0xffffffffu, s, 4);
            s += __shfl_xor_sync(0xffffffffu, s, 8);
            if ((tid & 15) == 0) sSum[row] += s;
        }
        __syncthreads();

        // ---- phase B: P @ V over this thread's j-half ----------------------
        const int jbeg = jh * 32;
        #pragma unroll 4
        for (int jj = 0; jj < 32; jj++) {
            int j = jbeg + jj;
            float p0 = sP[rgrp * 4 + 0][j];
            float p1 = sP[rgrp * 4 + 1][j];
            float p2 = sP[rgrp * 4 + 2][j];
            float p3 = sP[rgrp * 4 + 3][j];
            float4 va = *(const float4*)&sV[j][dseg * 4];
            float4 vb = *(const float4*)&sV[j][32 + dseg * 4];
            acc[0][0] = fmaf(p0, va.x, acc[0][0]);
            acc[0][1] = fmaf(p0, va.y, acc[0][1]);
            acc[0][2] = fmaf(p0, va.z, acc[0][2]);
            acc[0][3] = fmaf(p0, va.w, acc[0][3]);
            acc[0][4] = fmaf(p0, vb.x, acc[0][4]);
            acc[0][5] = fmaf(p0, vb.y, acc[0][5]);
            acc[0][6] = fmaf(p0, vb.z, acc[0][6]);
            acc[0][7] = fmaf(p0, vb.w, acc[0][7]);
            acc[1][0] = fmaf(p1, va.x, acc[1][0]);
            acc[1][1] = fmaf(p1, va.y, acc[1][1]);
            acc[1][2] = fmaf(p1, va.z, acc[1][2]);
            acc[1][3] = fmaf(p1, va.w, acc[1][3]);
            acc[1][4] = fmaf(p1, vb.x, acc[1][4]);
            acc[1][5] = fmaf(p1, vb.y, acc[1][5]);
            acc[1][6] = fmaf(p1, vb.z, acc[1][6]);
            acc[1][7] = fmaf(p1, vb.w, acc[1][7]);
            acc[2][0] = fmaf(p2, va.x, acc[2][0]);
            acc[2][1] = fmaf(p2, va.y, acc[2][1]);
            acc[2][2] = fmaf(p2, va.z, acc[2][2]);
            acc[2][3] = fmaf(p2, va.w, acc[2][3]);
            acc[2][4] = fmaf(p2, vb.x, acc[2][4]);
            acc[2][5] = fmaf(p2, vb.y, acc[2][5]);
            acc[2][6] = fmaf(p2, vb.z, acc[2][6]);
            acc[2][7] = fmaf(p2, vb.w, acc[2][7]);
            acc[3][0] = fmaf(p3, va.x, acc[3][0]);
            acc[3][1] = fmaf(p3, va.y, acc[3][1]);
            acc[3][2] = fmaf(p3, va.z, acc[3][2]);
            acc[3][3] = fmaf(p3, va.w, acc[3][3]);
            acc[3][4] = fmaf(p3, vb.x, acc[3][4]);
            acc[3][5] = fmaf(p3, vb.y, acc[3][5]);
            acc[3][6] = fmaf(p3, vb.z, acc[3][6]);
            acc[3][7] = fmaf(p3, vb.w, acc[3][7]);
        }
        __syncthreads();
    }

    // ---- epilogue: merge j-halves through smem, normalize, write -----------
    float* sAcc = &sP[0][0];   // reuse (4096 of 4352 floats)
    if (jh == 1) {
        float* dst = sAcc + (rgrp * 8 + dseg) * 32;
        #pragma unroll
        for (int i = 0; i < 4; i++)
            #pragma unroll
            for (int j = 0; j < 8; j++) dst[i * 8 + j] = acc[i][j];
    }
    __syncthreads();
    if (jh == 0) {
        const float* src = sAcc + (rgrp * 8 + dseg) * 32;
        #pragma unroll
        for (int rr = 0; rr < 4; rr++) {
            int r = rgrp * 4 + rr;
            float inv = 1.0f / sSum[r];
            float4 oa, ob;
            oa.x = (acc[rr][0] + src[rr * 8 + 0]) * inv;
            oa.y = (acc[rr][1] + src[rr * 8 + 1]) * inv;
            oa.z = (acc[rr][2] + src[rr * 8 + 2]) * inv;
            oa.w = (acc[rr][3] + src[rr * 8 + 3]) * inv;
            ob.x = (acc[rr][4] + src[rr * 8 + 4]) * inv;
            ob.y = (acc[rr][5] + src[rr * 8 + 5]) * inv;
            ob.z = (acc[rr][6] + src[rr * 8 + 6]) * inv;
            ob.w = (acc[rr][7] + src[rr * 8 + 7]) * inv;
            long obase = ((long)b * N_SEQ + i0 + r) * DIM + h * HD;
            *(float4*)&ctx[obase + dseg * 4]      = oa;
            *(float4*)&ctx[obase + 32 + dseg * 4] = ob;
        }
    }
}

// ---------------------------------------------------------------------------
extern "C" void kernel_launch(void* const* d_in, const int* in_sizes, int n_in,
                              void* d_out, int out_size)
{
    const float* x      = (const float*)d_in[0];
    const float* W_qkv  = (const float*)d_in[1];
    const float* W_v    = (const float*)d_in[2];
    const float* W_proj = (const float*)d_in[3];
    const float* b_proj = (const float*)d_in[4];
    const float* mixl   = (const float*)d_in[5];
    float* out = (float*)d_out;

    float *pY, *pV, *pCtx, *pS4;
    cudaGetSymbolAddress((void**)&pY,   g_Y);
    cudaGetSymbolAddress((void**)&pV,   g_V);
    cudaGetSymbolAddress((void**)&pCtx, g_ctx);
    cudaGetSymbolAddress((void**)&pS4,  g_S4);

    const int M = B_SZ * N_SEQ;
    dim3 blk(256);

    sgemm_tn<<<dim3(512 / 128, M / 128, 1), blk>>>(
        x, W_qkv, pY, nullptr, M, 512, DIM, DIM, DIM, 512, 1.0f,
        0, 0, 0, 0, 0, 1);

    sgemm_tn<<<dim3(DIM / 128, M / 128, 1), blk>>>(
        x, W_v, pV, nullptr, M, DIM, DIM, DIM, DIM, DIM, 1.0f,
        0, 0, 0, 0, 0, 1);

    sgemm_tn<<<dim3(N_SEQ / 128, N_SEQ / 128, B_SZ * KG), blk>>>(
        pY, pY + 256, pS4, nullptr, N_SEQ, N_SEQ, HD, 512, 512, N_SEQ, 0.125f,
        (long)N_SEQ * 512, 64, (long)N_SEQ * 512, 64, (long)N_SEQ * N_SEQ, KG);

    attn_kernel<<<dim3(N_SEQ / BR, HEFF, B_SZ), blk>>>(pS4, pV, mixl, pCtx);

    sgemm_tn<<<dim3(DIM / 128, M / 128, 1), blk>>>(
        pCtx, W_proj, out, b_proj, M, DIM, DIM, DIM, DIM, DIM, 1.0f,
        0, 0, 0, 0, 0, 1);
}

// round 5
// speedup vs baseline: 1.7270x; 1.5039x over previous
#include <cuda_runtime.h>
#include <cuda_bf16.h>
#include <cstdint>

// ---------------------------------------------------------------------------
// FiSHAttention: B=8, N=1024, dim=p=768, HEAD_DIM=64, K_GLOBAL=4, H_eff=12
//   1) Y   = x @ Wqkv[0:512].T             (HMMA split-bf16)
//   2) V   = x @ Wv.T                      (HMMA split-bf16)
//   3) S4  = 0.125 * qg @ kg.T             (HMMA split-bf16, 32 batched)
//   4) attention: combine+exp+PV           (fp32 FMA)
//   5) out = ctx @ Wproj.T + b_proj        (HMMA split-bf16)
// NOTE: harness compiles at sm_100 BASE (no 'a') -> tcgen05 unavailable;
// mma.sync bf16 (sm_80+ PTX) is the legal tensor-core path.
// Split-bf16: C = Ah Bh + Ah Bl + Al Bh, fp32 accum -> ~1e-5 rel err.
// ---------------------------------------------------------------------------

#define B_SZ   8
#define N_SEQ  1024
#define DIM    768
#define KG     4
#define HD     64
#define HEFF   12

__device__ float g_Y  [B_SZ * N_SEQ * 512];
__device__ float g_V  [B_SZ * N_SEQ * DIM];
__device__ float g_ctx[B_SZ * N_SEQ * DIM];
__device__ float g_S4 [(size_t)B_SZ * KG * N_SEQ * N_SEQ];

// ------------------------------ helpers ------------------------------------
__device__ __forceinline__ uint32_t smem_u32(const void* p) {
    uint32_t a;
    asm("{ .reg .u64 t; cvta.to.shared.u64 t, %1; cvt.u32.u64 %0, t; }"
        : "=r"(a) : "l"(p));
    return a;
}
__device__ __forceinline__ void ldsm_x4(uint32_t& r0, uint32_t& r1,
                                        uint32_t& r2, uint32_t& r3, uint32_t addr) {
    asm volatile("ldmatrix.sync.aligned.m8n8.x4.shared.b16 {%0,%1,%2,%3}, [%4];"
        : "=r"(r0), "=r"(r1), "=r"(r2), "=r"(r3) : "r"(addr));
}
__device__ __forceinline__ void mma16816(float* c, const uint32_t* a,
                                         const uint32_t* b) {
    asm volatile("mma.sync.aligned.m16n8k16.row.col.f32.bf16.bf16.f32 "
        "{%0,%1,%2,%3}, {%4,%5,%6,%7}, {%8,%9}, {%0,%1,%2,%3};"
        : "+f"(c[0]), "+f"(c[1]), "+f"(c[2]), "+f"(c[3])
        : "r"(a[0]), "r"(a[1]), "r"(a[2]), "r"(a[3]), "r"(b[0]), "r"(b[1]));
}

// exp/exp2 on the FMA pipe
__device__ __forceinline__ float fast_exp(float x) {
    x = fmaxf(x, -80.0f);
    const float L2E = 1.4426950408889634f;
    float t  = fmaf(x, L2E, 12582912.0f);
    float nf = t - 12582912.0f;
    int   ni = __float_as_int(t) - 0x4B400000;
    float f  = fmaf(x, L2E, -nf);
    f = fmaf(x, 1.9259629911266175e-8f, f);
    float p;
    p = 1.33335581e-3f;
    p = fmaf(p, f, 9.61812910e-3f);
    p = fmaf(p, f, 5.55041087e-2f);
    p = fmaf(p, f, 2.40226507e-1f);
    p = fmaf(p, f, 6.93147181e-1f);
    p = fmaf(p, f, 1.0f);
    return __int_as_float(__float_as_int(p) + (ni << 23));
}
__device__ __forceinline__ float fast_exp2(float y) {
    y = fmaxf(y, -100.0f);
    float t  = y + 12582912.0f;
    float nf = t - 12582912.0f;
    int   ni = __float_as_int(t) - 0x4B400000;
    float f  = y - nf;
    float p;
    p = 1.33335581e-3f;
    p = fmaf(p, f, 9.61812910e-3f);
    p = fmaf(p, f, 5.55041087e-2f);
    p = fmaf(p, f, 2.40226507e-1f);
    p = fmaf(p, f, 6.93147181e-1f);
    p = fmaf(p, f, 1.0f);
    return __int_as_float(__float_as_int(p) + (ni << 23));
}

// ===========================================================================
// HMMA split-bf16 TN GEMM. C = alpha * A[M,K] @ B[N,K]^T (+bias).
// CTA 128x128, 8 warps (4x2), warp tile 32x64, BK=32.
// smem tiles [128][40] bf16 (80B row stride -> conflict-free ldmatrix).
// ===========================================================================
#define BKC  32
#define TSTR 40

__global__ __launch_bounds__(256) void hmma_gemm(
    const float* __restrict__ A, const float* __restrict__ B,
    float* __restrict__ C, const float* __restrict__ bias,
    int K, int lda, int ldb, int ldc, float alpha,
    long sAo, long sAi, long sBo, long sBi, long sC, int innerMod)
{
    {
        int z = blockIdx.z;
        int outer = z / innerMod;
        int inner = z - outer * innerMod;
        A += (long)outer * sAo + (long)inner * sAi;
        B += (long)outer * sBo + (long)inner * sBi;
        C += (long)z * sC;
    }
    const int row0 = blockIdx.y * 128;
    const int col0 = blockIdx.x * 128;

    __shared__ __nv_bfloat16 sAh[128 * TSTR], sAl[128 * TSTR];
    __shared__ __nv_bfloat16 sBh[128 * TSTR], sBl[128 * TSTR];

    const int tid  = threadIdx.x;
    const int wid  = tid >> 5;
    const int lane = tid & 31;
    const int wm   = wid >> 1;   // 0..3 -> rows wm*32
    const int wn   = wid & 1;    // 0..1 -> cols wn*64

    // ldmatrix per-lane offsets
    const int a_r = lane & 15;
    const int a_k = (lane >> 4) << 3;
    const int b_r = (lane & 7) + ((lane >> 4) << 3);
    const int b_k = ((lane >> 3) & 1) << 3;

    const uint32_t uAh = smem_u32(sAh), uAl = smem_u32(sAl);
    const uint32_t uBh = smem_u32(sBh), uBl = smem_u32(sBl);

    float acc[2][8][4];
    #pragma unroll
    for (int i = 0; i < 2; i++)
        #pragma unroll
        for (int j = 0; j < 8; j++)
            #pragma unroll
            for (int q = 0; q < 4; q++) acc[i][j][q] = 0.0f;

    const int nch = K / BKC;
    for (int t = 0; t < nch; t++) {
        // ---- load f32, split to hi/lo bf16 smem tiles ----------------------
        #pragma unroll
        for (int m = 0; m < 2; m++) {
            const float* src = m ? B : A;
            const int    ld  = m ? ldb : lda;
            const int    rb  = m ? col0 : row0;
            __nv_bfloat16* ph = m ? sBh : sAh;
            __nv_bfloat16* pl = m ? sBl : sAl;
            #pragma unroll
            for (int it = 0; it < 4; it++) {
                int e = it * 256 + tid;
                int r = e >> 3;
                int c = (e & 7) << 2;
                float4 v = *(const float4*)&src[(long)(rb + r) * ld + t * BKC + c];
                __nv_bfloat16 h0 = __float2bfloat16(v.x);
                __nv_bfloat16 h1 = __float2bfloat16(v.y);
                __nv_bfloat16 h2 = __float2bfloat16(v.z);
                __nv_bfloat16 h3 = __float2bfloat16(v.w);
                __nv_bfloat16 l0 = __float2bfloat16(v.x - __bfloat162float(h0));
                __nv_bfloat16 l1 = __float2bfloat16(v.y - __bfloat162float(h1));
                __nv_bfloat16 l2 = __float2bfloat16(v.z - __bfloat162float(h2));
                __nv_bfloat16 l3 = __float2bfloat16(v.w - __bfloat162float(h3));
                uint2 hv, lv;
                hv.x = ((uint32_t)__bfloat16_as_ushort(h1) << 16) | __bfloat16_as_ushort(h0);
                hv.y = ((uint32_t)__bfloat16_as_ushort(h3) << 16) | __bfloat16_as_ushort(h2);
                lv.x = ((uint32_t)__bfloat16_as_ushort(l1) << 16) | __bfloat16_as_ushort(l0);
                lv.y = ((uint32_t)__bfloat16_as_ushort(l3) << 16) | __bfloat16_as_ushort(l2);
                *(uint2*)&ph[r * TSTR + c] = hv;
                *(uint2*)&pl[r * TSTR + c] = lv;
            }
        }
        __syncthreads();

        // ---- tensor-core math: HH, HL, LH ---------------------------------
        #pragma unroll
        for (int ks = 0; ks < 2; ks++) {
            const int k0 = ks * 16;
            const uint32_t aoff = (uint32_t)((wm * 32 + a_r) * TSTR + k0 + a_k) * 2;
            const uint32_t boff = (uint32_t)((wn * 64 + b_r) * TSTR + k0 + b_k) * 2;

            uint32_t af[2][4];
            ldsm_x4(af[0][0], af[0][1], af[0][2], af[0][3], uAh + aoff);
            ldsm_x4(af[1][0], af[1][1], af[1][2], af[1][3], uAh + aoff + 16 * TSTR * 2);

            uint32_t bh[8][2], bl[8][2];
            #pragma unroll
            for (int nb = 0; nb < 4; nb++) {
                ldsm_x4(bh[2*nb][0], bh[2*nb][1], bh[2*nb+1][0], bh[2*nb+1][1],
                        uBh + boff + nb * 16 * TSTR * 2);
                ldsm_x4(bl[2*nb][0], bl[2*nb][1], bl[2*nb+1][0], bl[2*nb+1][1],
                        uBl + boff + nb * 16 * TSTR * 2);
            }
            #pragma unroll
            for (int mf = 0; mf < 2; mf++)
                #pragma unroll
                for (int nf = 0; nf < 8; nf++) {
                    mma16816(acc[mf][nf], af[mf], bh[nf]);
                    mma16816(acc[mf][nf], af[mf], bl[nf]);
                }
            // LH: overwrite af with Al
            ldsm_x4(af[0][0], af[0][1], af[0][2], af[0][3], uAl + aoff);
            ldsm_x4(af[1][0], af[1][1], af[1][2], af[1][3], uAl + aoff + 16 * TSTR * 2);
            #pragma unroll
            for (int mf = 0; mf < 2; mf++)
                #pragma unroll
                for (int nf = 0; nf < 8; nf++)
                    mma16816(acc[mf][nf], af[mf], bh[nf]);
        }
        __syncthreads();
    }

    // ---- epilogue ----------------------------------------------------------
    const int qrow = lane >> 2;        // 0..7
    const int qcol = (lane & 3) << 1;  // 0,2,4,6
    #pragma unroll
    for (int mf = 0; mf < 2; mf++) {
        #pragma unroll
        for (int half = 0; half < 2; half++) {
            long r = row0 + wm * 32 + mf * 16 + half * 8 + qrow;
            #pragma unroll
            for (int nf = 0; nf < 8; nf++) {
                int n = col0 + wn * 64 + nf * 8 + qcol;
                float2 o;
                o.x = alpha * acc[mf][nf][half * 2 + 0];
                o.y = alpha * acc[mf][nf][half * 2 + 1];
                if (bias) { o.x += bias[n]; o.y += bias[n + 1]; }
                *(float2*)&C[r * ldc + n] = o;
            }
        }
    }
}

// ===========================================================================
// Fused attention (v3, unchanged).
// ===========================================================================
#define BR 64
#define BC 64
#define PSTR 68

__global__ __launch_bounds__(256) void attn_kernel(
    const float* __restrict__ S4, const float* __restrict__ V,
    const float* __restrict__ mixl, float* __restrict__ ctx)
{
    const int ib = blockIdx.x;
    const int h  = blockIdx.y;
    const int b  = blockIdx.z;

    __shared__ float sP[BR][PSTR];
    __shared__ float sV[BC][HD];
    __shared__ float sSum[BR];
    __shared__ float sMix[4];

    const int tid = threadIdx.x;

    if (tid < 4) {
        float l0 = mixl[h * 4 + 0], l1 = mixl[h * 4 + 1];
        float l2 = mixl[h * 4 + 2], l3 = mixl[h * 4 + 3];
        float m  = fmaxf(fmaxf(l0, l1), fmaxf(l2, l3));
        float e0 = fast_exp(l0 - m), e1 = fast_exp(l1 - m);
        float e2 = fast_exp(l2 - m), e3 = fast_exp(l3 - m);
        float s  = e0 + e1 + e2 + e3;
        float mine = (tid == 0) ? e0 : (tid == 1) ? e1 : (tid == 2) ? e2 : e3;
        sMix[tid] = (mine / s) * 1.4426950408889634f;
    }
    if (tid < BR) sSum[tid] = 0.0f;
    __syncthreads();

    const float mx0 = sMix[0], mx1 = sMix[1], mx2 = sMix[2], mx3 = sMix[3];
    const int i0 = ib * BR;
    const int jh   = tid >> 7;
    const int rgrp = (tid >> 3) & 15;
    const int dseg = tid & 7;

    float acc[4][8];
    #pragma unroll
    for (int i = 0; i < 4; i++)
        #pragma unroll
        for (int j = 0; j < 8; j++) acc[i][j] = 0.0f;

    const float* S4b = S4 + (long)b * KG * N_SEQ * N_SEQ;
    const float* Vb  = V + (long)b * N_SEQ * DIM + h * HD;
    const long   PL  = (long)N_SEQ * N_SEQ;

    for (int j0 = 0; j0 < N_SEQ; j0 += BC) {
        #pragma unroll
        for (int it = 0; it < 4; it++) {
            int e = it * 256 + tid;
            int j = e >> 4, dq = (e & 15) << 2;
            *(float4*)&sV[j][dq] = *(const float4*)&Vb[(long)(j0 + j) * DIM + dq];
        }

        #pragma unroll
        for (int c = 0; c < 4; c++) {
            int row  = c * 16 + (tid >> 4);
            int col  = (tid & 15) << 2;
            const float* base = S4b + (long)(i0 + row) * N_SEQ + j0 + col;
            float4 a  = *(const float4*)(base);
            float4 p1 = *(const float4*)(base + PL);
            float4 p2 = *(const float4*)(base + 2 * PL);
            float4 p3 = *(const float4*)(base + 3 * PL);
            float4 pr;
            pr.x = fast_exp2(fmaf(mx3, p3.x, fmaf(mx2, p2.x, fmaf(mx1, p1.x, mx0 * a.x))));
            pr.y = fast_exp2(fmaf(mx3, p3.y, fmaf(mx2, p2.y, fmaf(mx1, p1.y, mx0 * a.y))));
            pr.z = fast_exp2(fmaf(mx3, p3.z, fmaf(mx2, p2.z, fmaf(mx1, p1.z, mx0 * a.z))));
            pr.w = fast_exp2(fmaf(mx3, p3.w, fmaf(mx2, p2.w, fmaf(mx1, p1.w, mx0 * a.w))));
            *(float4*)&sP[row][col] = pr;

            float s = (pr.x + pr.y) + (pr.z + pr.w);
            s += __shfl_xor_sync(0xffffffffu, s, 1);
            s += __shfl_xor_sync(0xffffffffu, s, 2);
            s += __shfl_xor_sync(0xffffffffu, s, 4);
            s += __shfl_xor_sync(0xffffffffu, s, 8);
            if ((tid & 15) == 0) sSum[row] += s;
        }
        __syncthreads();

        const int jbeg = jh * 32;
        #pragma unroll 4
        for (int jj = 0; jj < 32; jj++) {
            int j = jbeg + jj;
            float p0 = sP[rgrp * 4 + 0][j];
            float p1 = sP[rgrp * 4 + 1][j];
            float p2 = sP[rgrp * 4 + 2][j];
            float p3 = sP[rgrp * 4 + 3][j];
            float4 va = *(const float4*)&sV[j][dseg * 4];
            float4 vb = *(const float4*)&sV[j][32 + dseg * 4];
            acc[0][0] = fmaf(p0, va.x, acc[0][0]);
            acc[0][1] = fmaf(p0, va.y, acc[0][1]);
            acc[0][2] = fmaf(p0, va.z, acc[0][2]);
            acc[0][3] = fmaf(p0, va.w, acc[0][3]);
            acc[0][4] = fmaf(p0, vb.x, acc[0][4]);
            acc[0][5] = fmaf(p0, vb.y, acc[0][5]);
            acc[0][6] = fmaf(p0, vb.z, acc[0][6]);
            acc[0][7] = fmaf(p0, vb.w, acc[0][7]);
            acc[1][0] = fmaf(p1, va.x, acc[1][0]);
            acc[1][1] = fmaf(p1, va.y, acc[1][1]);
            acc[1][2] = fmaf(p1, va.z, acc[1][2]);
            acc[1][3] = fmaf(p1, va.w, acc[1][3]);
            acc[1][4] = fmaf(p1, vb.x, acc[1][4]);
            acc[1][5] = fmaf(p1, vb.y, acc[1][5]);
            acc[1][6] = fmaf(p1, vb.z, acc[1][6]);
            acc[1][7] = fmaf(p1, vb.w, acc[1][7]);
            acc[2][0] = fmaf(p2, va.x, acc[2][0]);
            acc[2][1] = fmaf(p2, va.y, acc[2][1]);
            acc[2][2] = fmaf(p2, va.z, acc[2][2]);
            acc[2][3] = fmaf(p2, va.w, acc[2][3]);
            acc[2][4] = fmaf(p2, vb.x, acc[2][4]);
            acc[2][5] = fmaf(p2, vb.y, acc[2][5]);
            acc[2][6] = fmaf(p2, vb.z, acc[2][6]);
            acc[2][7] = fmaf(p2, vb.w, acc[2][7]);
            acc[3][0] = fmaf(p3, va.x, acc[3][0]);
            acc[3][1] = fmaf(p3, va.y, acc[3][1]);
            acc[3][2] = fmaf(p3, va.z, acc[3][2]);
            acc[3][3] = fmaf(p3, va.w, acc[3][3]);
            acc[3][4] = fmaf(p3, vb.x, acc[3][4]);
            acc[3][5] = fmaf(p3, vb.y, acc[3][5]);
            acc[3][6] = fmaf(p3, vb.z, acc[3][6]);
            acc[3][7] = fmaf(p3, vb.w, acc[3][7]);
        }
        __syncthreads();
    }

    float* sAcc = &sP[0][0];
    if (jh == 1) {
        float* dst = sAcc + (rgrp * 8 + dseg) * 32;
        #pragma unroll
        for (int i = 0; i < 4; i++)
            #pragma unroll
            for (int j = 0; j < 8; j++) dst[i * 8 + j] = acc[i][j];
    }
    __syncthreads();
    if (jh == 0) {
        const float* src = sAcc + (rgrp * 8 + dseg) * 32;
        #pragma unroll
        for (int rr = 0; rr < 4; rr++) {
            int r = rgrp * 4 + rr;
            float inv = 1.0f / sSum[r];
            float4 oa, ob;
            oa.x = (acc[rr][0] + src[rr * 8 + 0]) * inv;
            oa.y = (acc[rr][1] + src[rr * 8 + 1]) * inv;
            oa.z = (acc[rr][2] + src[rr * 8 + 2]) * inv;
            oa.w = (acc[rr][3] + src[rr * 8 + 3]) * inv;
            ob.x = (acc[rr][4] + src[rr * 8 + 4]) * inv;
            ob.y = (acc[rr][5] + src[rr * 8 + 5]) * inv;
            ob.z = (acc[rr][6] + src[rr * 8 + 6]) * inv;
            ob.w = (acc[rr][7] + src[rr * 8 + 7]) * inv;
            long obase = ((long)b * N_SEQ + i0 + r) * DIM + h * HD;
            *(float4*)&ctx[obase + dseg * 4]      = oa;
            *(float4*)&ctx[obase + 32 + dseg * 4] = ob;
        }
    }
}

// ---------------------------------------------------------------------------
extern "C" void kernel_launch(void* const* d_in, const int* in_sizes, int n_in,
                              void* d_out, int out_size)
{
    const float* x      = (const float*)d_in[0];
    const float* W_qkv  = (const float*)d_in[1];
    const float* W_v    = (const float*)d_in[2];
    const float* W_proj = (const float*)d_in[3];
    const float* b_proj = (const float*)d_in[4];
    const float* mixl   = (const float*)d_in[5];
    float* out = (float*)d_out;

    float *pY, *pV, *pCtx, *pS4;
    cudaGetSymbolAddress((void**)&pY,   g_Y);
    cudaGetSymbolAddress((void**)&pV,   g_V);
    cudaGetSymbolAddress((void**)&pCtx, g_ctx);
    cudaGetSymbolAddress((void**)&pS4,  g_S4);

    dim3 blk(256);

    // 1) Y = x @ W_qkv[0:512].T    M=8192 N=512 K=768
    hmma_gemm<<<dim3(4, 64, 1), blk>>>(
        x, W_qkv, pY, nullptr, DIM, DIM, DIM, 512, 1.0f, 0, 0, 0, 0, 0, 1);

    // 2) V = x @ W_v.T             M=8192 N=768 K=768
    hmma_gemm<<<dim3(6, 64, 1), blk>>>(
        x, W_v, pV, nullptr, DIM, DIM, DIM, DIM, 1.0f, 0, 0, 0, 0, 0, 1);

    // 3) S4 = 0.125 * q @ k.T      32 x (1024x1024x64)
    hmma_gemm<<<dim3(8, 8, B_SZ * KG), blk>>>(
        pY, pY + 256, pS4, nullptr, HD, 512, 512, N_SEQ, 0.125f,
        (long)N_SEQ * 512, 64, (long)N_SEQ * 512, 64, (long)N_SEQ * N_SEQ, KG);

    // 4) attention
    attn_kernel<<<dim3(N_SEQ / BR, HEFF, B_SZ), blk>>>(pS4, pV, mixl, pCtx);

    // 5) out = ctx @ W_proj.T + b  M=8192 N=768 K=768
    hmma_gemm<<<dim3(6, 64, 1), blk>>>(
        pCtx, W_proj, out, b_proj, DIM, DIM, DIM, DIM, 1.0f, 0, 0, 0, 0, 0, 1);
}

// round 6
// speedup vs baseline: 2.1099x; 1.2217x over previous
#include <cuda_runtime.h>
#include <cuda_bf16.h>
#include <cstdint>

// ---------------------------------------------------------------------------
// FiSHAttention: B=8, N=1024, dim=p=768, HEAD_DIM=64, K_GLOBAL=4, H_eff=12
//   1) Y    = x @ Wqkv[0:512].T          (HMMA split-bf16, 3-pass)
//   2) V    = x @ Wv.T                   (HMMA split-bf16)
//   2b) Vt  = transpose+bf16split of V   (per-head [d][j] hi/lo)
//   3) S4   = 0.125 * qg @ kg.T          (HMMA split-bf16, 32 batched)
//   4) attn: combine+exp2 (FMA pipe) + PV on HMMA (split-bf16, 3-pass),
//            2 heads/CTA so S4 planes are read once per tile
//   5) out  = ctx @ Wproj.T + b_proj     (HMMA split-bf16)
// ---------------------------------------------------------------------------

#define B_SZ   8
#define N_SEQ  1024
#define DIM    768
#define KG     4
#define HD     64
#define HEFF   12

__device__ float g_Y  [B_SZ * N_SEQ * 512];
__device__ float g_V  [B_SZ * N_SEQ * DIM];
__device__ float g_ctx[B_SZ * N_SEQ * DIM];
__device__ float g_S4 [(size_t)B_SZ * KG * N_SEQ * N_SEQ];
__device__ __nv_bfloat16 g_Vth[(size_t)B_SZ * HEFF * HD * N_SEQ];  // 12.6MB
__device__ __nv_bfloat16 g_Vtl[(size_t)B_SZ * HEFF * HD * N_SEQ];

// ------------------------------ helpers ------------------------------------
__device__ __forceinline__ uint32_t smem_u32(const void* p) {
    uint32_t a;
    asm("{ .reg .u64 t; cvta.to.shared.u64 t, %1; cvt.u32.u64 %0, t; }"
        : "=r"(a) : "l"(p));
    return a;
}
__device__ __forceinline__ void ldsm_x4(uint32_t& r0, uint32_t& r1,
                                        uint32_t& r2, uint32_t& r3, uint32_t addr) {
    asm volatile("ldmatrix.sync.aligned.m8n8.x4.shared.b16 {%0,%1,%2,%3}, [%4];"
        : "=r"(r0), "=r"(r1), "=r"(r2), "=r"(r3) : "r"(addr));
}
__device__ __forceinline__ void mma16816(float* c, const uint32_t* a,
                                         const uint32_t* b) {
    asm volatile("mma.sync.aligned.m16n8k16.row.col.f32.bf16.bf16.f32 "
        "{%0,%1,%2,%3}, {%4,%5,%6,%7}, {%8,%9}, {%0,%1,%2,%3};"
        : "+f"(c[0]), "+f"(c[1]), "+f"(c[2]), "+f"(c[3])
        : "r"(a[0]), "r"(a[1]), "r"(a[2]), "r"(a[3]), "r"(b[0]), "r"(b[1]));
}

__device__ __forceinline__ float fast_exp(float x) {
    x = fmaxf(x, -80.0f);
    const float L2E = 1.4426950408889634f;
    float t  = fmaf(x, L2E, 12582912.0f);
    float nf = t - 12582912.0f;
    int   ni = __float_as_int(t) - 0x4B400000;
    float f  = fmaf(x, L2E, -nf);
    f = fmaf(x, 1.9259629911266175e-8f, f);
    float p;
    p = 1.33335581e-3f;
    p = fmaf(p, f, 9.61812910e-3f);
    p = fmaf(p, f, 5.55041087e-2f);
    p = fmaf(p, f, 2.40226507e-1f);
    p = fmaf(p, f, 6.93147181e-1f);
    p = fmaf(p, f, 1.0f);
    return __int_as_float(__float_as_int(p) + (ni << 23));
}
__device__ __forceinline__ float fast_exp2(float y) {
    y = fmaxf(y, -100.0f);
    float t  = y + 12582912.0f;
    float nf = t - 12582912.0f;
    int   ni = __float_as_int(t) - 0x4B400000;
    float f  = y - nf;
    float p;
    p = 1.33335581e-3f;
    p = fmaf(p, f, 9.61812910e-3f);
    p = fmaf(p, f, 5.55041087e-2f);
    p = fmaf(p, f, 2.40226507e-1f);
    p = fmaf(p, f, 6.93147181e-1f);
    p = fmaf(p, f, 1.0f);
    return __int_as_float(__float_as_int(p) + (ni << 23));
}

// ===========================================================================
// HMMA split-bf16 TN GEMM (unchanged from round 5; ~237 TF/s).
// ===========================================================================
#define BKC  32
#define TSTR 40

__global__ __launch_bounds__(256) void hmma_gemm(
    const float* __restrict__ A, const float* __restrict__ B,
    float* __restrict__ C, const float* __restrict__ bias,
    int K, int lda, int ldb, int ldc, float alpha,
    long sAo, long sAi, long sBo, long sBi, long sC, int innerMod)
{
    {
        int z = blockIdx.z;
        int outer = z / innerMod;
        int inner = z - outer * innerMod;
        A += (long)outer * sAo + (long)inner * sAi;
        B += (long)outer * sBo + (long)inner * sBi;
        C += (long)z * sC;
    }
    const int row0 = blockIdx.y * 128;
    const int col0 = blockIdx.x * 128;

    __shared__ __nv_bfloat16 sAh[128 * TSTR], sAl[128 * TSTR];
    __shared__ __nv_bfloat16 sBh[128 * TSTR], sBl[128 * TSTR];

    const int tid  = threadIdx.x;
    const int wid  = tid >> 5;
    const int lane = tid & 31;
    const int wm   = wid >> 1;
    const int wn   = wid & 1;

    const int a_r = lane & 15;
    const int a_k = (lane >> 4) << 3;
    const int b_r = (lane & 7) + ((lane >> 4) << 3);
    const int b_k = ((lane >> 3) & 1) << 3;

    const uint32_t uAh = smem_u32(sAh), uAl = smem_u32(sAl);
    const uint32_t uBh = smem_u32(sBh), uBl = smem_u32(sBl);

    float acc[2][8][4];
    #pragma unroll
    for (int i = 0; i < 2; i++)
        #pragma unroll
        for (int j = 0; j < 8; j++)
            #pragma unroll
            for (int q = 0; q < 4; q++) acc[i][j][q] = 0.0f;

    const int nch = K / BKC;
    for (int t = 0; t < nch; t++) {
        #pragma unroll
        for (int m = 0; m < 2; m++) {
            const float* src = m ? B : A;
            const int    ld  = m ? ldb : lda;
            const int    rb  = m ? col0 : row0;
            __nv_bfloat16* ph = m ? sBh : sAh;
            __nv_bfloat16* pl = m ? sBl : sAl;
            #pragma unroll
            for (int it = 0; it < 4; it++) {
                int e = it * 256 + tid;
                int r = e >> 3;
                int c = (e & 7) << 2;
                float4 v = *(const float4*)&src[(long)(rb + r) * ld + t * BKC + c];
                __nv_bfloat16 h0 = __float2bfloat16(v.x);
                __nv_bfloat16 h1 = __float2bfloat16(v.y);
                __nv_bfloat16 h2 = __float2bfloat16(v.z);
                __nv_bfloat16 h3 = __float2bfloat16(v.w);
                __nv_bfloat16 l0 = __float2bfloat16(v.x - __bfloat162float(h0));
                __nv_bfloat16 l1 = __float2bfloat16(v.y - __bfloat162float(h1));
                __nv_bfloat16 l2 = __float2bfloat16(v.z - __bfloat162float(h2));
                __nv_bfloat16 l3 = __float2bfloat16(v.w - __bfloat162float(h3));
                uint2 hv, lv;
                hv.x = ((uint32_t)__bfloat16_as_ushort(h1) << 16) | __bfloat16_as_ushort(h0);
                hv.y = ((uint32_t)__bfloat16_as_ushort(h3) << 16) | __bfloat16_as_ushort(h2);
                lv.x = ((uint32_t)__bfloat16_as_ushort(l1) << 16) | __bfloat16_as_ushort(l0);
                lv.y = ((uint32_t)__bfloat16_as_ushort(l3) << 16) | __bfloat16_as_ushort(l2);
                *(uint2*)&ph[r * TSTR + c] = hv;
                *(uint2*)&pl[r * TSTR + c] = lv;
            }
        }
        __syncthreads();

        #pragma unroll
        for (int ks = 0; ks < 2; ks++) {
            const int k0 = ks * 16;
            const uint32_t aoff = (uint32_t)((wm * 32 + a_r) * TSTR + k0 + a_k) * 2;
            const uint32_t boff = (uint32_t)((wn * 64 + b_r) * TSTR + k0 + b_k) * 2;

            uint32_t af[2][4];
            ldsm_x4(af[0][0], af[0][1], af[0][2], af[0][3], uAh + aoff);
            ldsm_x4(af[1][0], af[1][1], af[1][2], af[1][3], uAh + aoff + 16 * TSTR * 2);

            uint32_t bh[8][2], bl[8][2];
            #pragma unroll
            for (int nb = 0; nb < 4; nb++) {
                ldsm_x4(bh[2*nb][0], bh[2*nb][1], bh[2*nb+1][0], bh[2*nb+1][1],
                        uBh + boff + nb * 16 * TSTR * 2);
                ldsm_x4(bl[2*nb][0], bl[2*nb][1], bl[2*nb+1][0], bl[2*nb+1][1],
                        uBl + boff + nb * 16 * TSTR * 2);
            }
            #pragma unroll
            for (int mf = 0; mf < 2; mf++)
                #pragma unroll
                for (int nf = 0; nf < 8; nf++) {
                    mma16816(acc[mf][nf], af[mf], bh[nf]);
                    mma16816(acc[mf][nf], af[mf], bl[nf]);
                }
            ldsm_x4(af[0][0], af[0][1], af[0][2], af[0][3], uAl + aoff);
            ldsm_x4(af[1][0], af[1][1], af[1][2], af[1][3], uAl + aoff + 16 * TSTR * 2);
            #pragma unroll
            for (int mf = 0; mf < 2; mf++)
                #pragma unroll
                for (int nf = 0; nf < 8; nf++)
                    mma16816(acc[mf][nf], af[mf], bh[nf]);
        }
        __syncthreads();
    }

    const int qrow = lane >> 2;
    const int qcol = (lane & 3) << 1;
    #pragma unroll
    for (int mf = 0; mf < 2; mf++) {
        #pragma unroll
        for (int half = 0; half < 2; half++) {
            long r = row0 + wm * 32 + mf * 16 + half * 8 + qrow;
            #pragma unroll
            for (int nf = 0; nf < 8; nf++) {
                int n = col0 + wn * 64 + nf * 8 + qcol;
                float2 o;
                o.x = alpha * acc[mf][nf][half * 2 + 0];
                o.y = alpha * acc[mf][nf][half * 2 + 1];
                if (bias) { o.x += bias[n]; o.y += bias[n + 1]; }
                *(float2*)&C[r * ldc + n] = o;
            }
        }
    }
}

// ===========================================================================
// V transpose + bf16 hi/lo split: g_V[b,j,h*64+d] -> g_Vt{h,l}[(b*12+h)*64+d][j]
// Grid (16 jt, 96 bh), 256 threads.
// ===========================================================================
__global__ __launch_bounds__(256) void vconvert(
    const float* __restrict__ V, __nv_bfloat16* __restrict__ Vth,
    __nv_bfloat16* __restrict__ Vtl)
{
    const int j0   = blockIdx.x * 64;
    const int bhid = blockIdx.y;
    const int b    = bhid / HEFF;
    const int h    = bhid - b * HEFF;

    __shared__ float sT[64][68];
    const int tid = threadIdx.x;

    #pragma unroll
    for (int it = 0; it < 4; it++) {
        int e = it * 256 + tid;
        int j = e >> 4, dq = (e & 15) << 2;
        float4 v = *(const float4*)&V[((long)b * N_SEQ + j0 + j) * DIM + h * HD + dq];
        sT[dq + 0][j] = v.x; sT[dq + 1][j] = v.y;
        sT[dq + 2][j] = v.z; sT[dq + 3][j] = v.w;
    }
    __syncthreads();

    const int d = tid >> 2, jseg = (tid & 3) << 4;
    ushort hv[16], lv[16];
    #pragma unroll
    for (int t = 0; t < 16; t++) {
        float f = sT[d][jseg + t];
        __nv_bfloat16 hb = __float2bfloat16(f);
        __nv_bfloat16 lb = __float2bfloat16(f - __bfloat162float(hb));
        hv[t] = __bfloat16_as_ushort(hb);
        lv[t] = __bfloat16_as_ushort(lb);
    }
    size_t dst = ((size_t)bhid * HD + d) * N_SEQ + j0 + jseg;
    *(uint4*)&Vth[dst]     = *(uint4*)&hv[0];
    *(uint4*)&Vth[dst + 8] = *(uint4*)&hv[8];
    *(uint4*)&Vtl[dst]     = *(uint4*)&lv[0];
    *(uint4*)&Vtl[dst + 8] = *(uint4*)&lv[8];
}

// ===========================================================================
// Attention v4: 2 heads/CTA, PV on HMMA. Grid (16 ib, 6 hg, 8 b), 256 thr.
// Per 64-col j-tile: [sync; load V bf16 tiles + phase A (S4 read once,
// combine+exp2 for both heads, split bf16 P to smem); sync; MMA both heads].
// smem: V 4x9216 + P 4x9216 + sums = ~74.3KB dynamic -> 2 CTA/SM.
// ===========================================================================
#define PBY 9216            // one 64x72 bf16 buffer
#define OFF_V 0             // [Vh h0][Vh h1][Vl h0][Vl h1]
#define OFF_P (4 * PBY)     // [Ph h0][Ph h1][Pl h0][Pl h1]
#define OFF_SUM (8 * PBY)   // float[2][64]
#define OFF_MIX (OFF_SUM + 512)
#define ATTN_SMEM (OFF_MIX + 64)

__global__ __launch_bounds__(256, 2) void attn_kernel(
    const float* __restrict__ S4,
    const __nv_bfloat16* __restrict__ Vth, const __nv_bfloat16* __restrict__ Vtl,
    const float* __restrict__ mixl, float* __restrict__ ctx)
{
    const int ib = blockIdx.x;
    const int hg = blockIdx.y;
    const int b  = blockIdx.z;

    extern __shared__ char sm[];
    const uint32_t sb = smem_u32(sm);
    float* sSum = (float*)(sm + OFF_SUM);
    float* sMix = (float*)(sm + OFF_MIX);

    const int tid  = threadIdx.x;
    const int wid  = tid >> 5;
    const int lane = tid & 31;
    const int wr   = wid >> 1;       // 0..3: row band wr*16
    const int wc   = wid & 1;        // 0..1: col band wc*32
    const int a_r  = lane & 15;
    const int a_k  = (lane >> 4) << 3;
    const int b_r  = (lane & 7) + ((lane >> 4) << 3);
    const int b_k  = ((lane >> 3) & 1) << 3;

    if (tid < 128) sSum[tid] = 0.0f;
    if (tid < 8) {
        int hh = tid >> 2, k = tid & 3;
        const float* ml = mixl + (hg * 2 + hh) * 4;
        float l0 = ml[0], l1 = ml[1], l2 = ml[2], l3 = ml[3];
        float m  = fmaxf(fmaxf(l0, l1), fmaxf(l2, l3));
        float e0 = fast_exp(l0 - m), e1 = fast_exp(l1 - m);
        float e2 = fast_exp(l2 - m), e3 = fast_exp(l3 - m);
        float s  = e0 + e1 + e2 + e3;
        float mine = (k == 0) ? e0 : (k == 1) ? e1 : (k == 2) ? e2 : e3;
        sMix[hh * 4 + k] = (mine / s) * 1.4426950408889634f;
    }

    const int i0   = ib * 64;
    const int arow = tid >> 2;
    const int aq   = tid & 3;
    const float* S4b = S4 + (long)b * KG * N_SEQ * N_SEQ;
    const long   PL  = (long)N_SEQ * N_SEQ;
    const size_t vbase0 = ((size_t)(b * HEFF + hg * 2 + 0)) * HD * N_SEQ;
    const size_t vbase1 = ((size_t)(b * HEFF + hg * 2 + 1)) * HD * N_SEQ;

    float acc[2][4][4];
    #pragma unroll
    for (int i = 0; i < 2; i++)
        #pragma unroll
        for (int j = 0; j < 4; j++)
            #pragma unroll
            for (int q = 0; q < 4; q++) acc[i][j][q] = 0.0f;

    for (int j0 = 0; j0 < N_SEQ; j0 += 64) {
        __syncthreads();   // prev MMAs done before overwriting V/P

        // ---- load V bf16 tiles: 4 buffers x 512 uint4 ----------------------
        #pragma unroll
        for (int it = 0; it < 8; it++) {
            int idx = it * 256 + tid;
            int bufid = idx >> 9;            // 0:Vh h0 1:Vh h1 2:Vl h0 3:Vl h1
            int r = (idx >> 3) & 63;
            int q = idx & 7;
            const __nv_bfloat16* src =
                (bufid & 2) ? Vtl : Vth;
            size_t so = ((bufid & 1) ? vbase1 : vbase0) + (size_t)r * N_SEQ + j0 + q * 8;
            *(uint4*)(sm + OFF_V + bufid * PBY + (r * 72 + q * 8) * 2) =
                *(const uint4*)&src[so];
        }

        // ---- phase A: read 4 planes once, both heads combine+exp2 ----------
        {
            const float mx00 = sMix[0], mx01 = sMix[1], mx02 = sMix[2], mx03 = sMix[3];
            const float mx10 = sMix[4], mx11 = sMix[5], mx12 = sMix[6], mx13 = sMix[7];
            const float* base = S4b + (long)(i0 + arow) * N_SEQ + j0 + aq * 16;
            float s0 = 0.0f, s1 = 0.0f;
            #pragma unroll
            for (int c = 0; c < 4; c++) {
                float4 a  = *(const float4*)(base + c * 4);
                float4 p1 = *(const float4*)(base + PL + c * 4);
                float4 p2 = *(const float4*)(base + 2 * PL + c * 4);
                float4 p3 = *(const float4*)(base + 3 * PL + c * 4);
                const uint32_t po = (uint32_t)(arow * 72 + aq * 16 + c * 4) * 2;
                #pragma unroll
                for (int hh = 0; hh < 2; hh++) {
                    float m0 = hh ? mx10 : mx00, m1 = hh ? mx11 : mx01;
                    float m2 = hh ? mx12 : mx02, m3 = hh ? mx13 : mx03;
                    float q0 = fast_exp2(fmaf(m3, p3.x, fmaf(m2, p2.x, fmaf(m1, p1.x, m0 * a.x))));
                    float q1 = fast_exp2(fmaf(m3, p3.y, fmaf(m2, p2.y, fmaf(m1, p1.y, m0 * a.y))));
                    float q2 = fast_exp2(fmaf(m3, p3.z, fmaf(m2, p2.z, fmaf(m1, p1.z, m0 * a.z))));
                    float q3 = fast_exp2(fmaf(m3, p3.w, fmaf(m2, p2.w, fmaf(m1, p1.w, m0 * a.w))));
                    if (hh) s1 += (q0 + q1) + (q2 + q3);
                    else    s0 += (q0 + q1) + (q2 + q3);
                    __nv_bfloat16 h0 = __float2bfloat16(q0);
                    __nv_bfloat16 h1 = __float2bfloat16(q1);
                    __nv_bfloat16 h2 = __float2bfloat16(q2);
                    __nv_bfloat16 h3 = __float2bfloat16(q3);
                    __nv_bfloat16 l0 = __float2bfloat16(q0 - __bfloat162float(h0));
                    __nv_bfloat16 l1 = __float2bfloat16(q1 - __bfloat162float(h1));
                    __nv_bfloat16 l2 = __float2bfloat16(q2 - __bfloat162float(h2));
                    __nv_bfloat16 l3 = __float2bfloat16(q3 - __bfloat162float(h3));
                    uint2 hv, lv;
                    hv.x = ((uint32_t)__bfloat16_as_ushort(h1) << 16) | __bfloat16_as_ushort(h0);
                    hv.y = ((uint32_t)__bfloat16_as_ushort(h3) << 16) | __bfloat16_as_ushort(h2);
                    lv.x = ((uint32_t)__bfloat16_as_ushort(l1) << 16) | __bfloat16_as_ushort(l0);
                    lv.y = ((uint32_t)__bfloat16_as_ushort(l3) << 16) | __bfloat16_as_ushort(l2);
                    *(uint2*)(sm + OFF_P + hh * PBY + po)       = hv;
                    *(uint2*)(sm + OFF_P + (2 + hh) * PBY + po) = lv;
                }
            }
            s0 += __shfl_xor_sync(0xffffffffu, s0, 1);
            s0 += __shfl_xor_sync(0xffffffffu, s0, 2);
            s1 += __shfl_xor_sync(0xffffffffu, s1, 1);
            s1 += __shfl_xor_sync(0xffffffffu, s1, 2);
            if (aq == 0) {
                sSum[arow]      += s0;
                sSum[64 + arow] += s1;
            }
        }
        __syncthreads();

        // ---- MMA: both heads, 3-pass split ---------------------------------
        #pragma unroll
        for (int hh = 0; hh < 2; hh++) {
            const uint32_t uPh = sb + OFF_P + hh * PBY;
            const uint32_t uPl = uPh + 2 * PBY;
            const uint32_t uVh = sb + OFF_V + hh * PBY;
            const uint32_t uVl = uVh + 2 * PBY;
            #pragma unroll
            for (int ks = 0; ks < 4; ks++) {
                const int k0 = ks * 16;
                const uint32_t aoff = (uint32_t)((wr * 16 + a_r) * 72 + k0 + a_k) * 2;
                const uint32_t boff = (uint32_t)((wc * 32 + b_r) * 72 + k0 + b_k) * 2;
                uint32_t ah[4], al[4];
                ldsm_x4(ah[0], ah[1], ah[2], ah[3], uPh + aoff);
                ldsm_x4(al[0], al[1], al[2], al[3], uPl + aoff);
                uint32_t bh[4][2], bl[4][2];
                #pragma unroll
                for (int nb = 0; nb < 2; nb++) {
                    ldsm_x4(bh[2*nb][0], bh[2*nb][1], bh[2*nb+1][0], bh[2*nb+1][1],
                            uVh + boff + nb * 16 * 72 * 2);
                    ldsm_x4(bl[2*nb][0], bl[2*nb][1], bl[2*nb+1][0], bl[2*nb+1][1],
                            uVl + boff + nb * 16 * 72 * 2);
                }
                #pragma unroll
                for (int nf = 0; nf < 4; nf++) {
                    mma16816(acc[hh][nf], ah, bh[nf]);
                    mma16816(acc[hh][nf], ah, bl[nf]);
                    mma16816(acc[hh][nf], al, bh[nf]);
                }
            }
        }
    }
    __syncthreads();

    // ---- epilogue: normalize, write ctx ------------------------------------
    const int qrow = lane >> 2;
    const int qcol = (lane & 3) << 1;
    #pragma unroll
    for (int hh = 0; hh < 2; hh++) {
        #pragma unroll
        for (int half = 0; half < 2; half++) {
            int r = wr * 16 + half * 8 + qrow;
            float inv = 1.0f / sSum[hh * 64 + r];
            long obase = ((long)b * N_SEQ + i0 + r) * DIM + (hg * 2 + hh) * HD;
            #pragma unroll
            for (int nf = 0; nf < 4; nf++) {
                int n = wc * 32 + nf * 8 + qcol;
                float2 o;
                o.x = acc[hh][nf][half * 2 + 0] * inv;
                o.y = acc[hh][nf][half * 2 + 1] * inv;
                *(float2*)&ctx[obase + n] = o;
            }
        }
    }
}

// ---------------------------------------------------------------------------
extern "C" void kernel_launch(void* const* d_in, const int* in_sizes, int n_in,
                              void* d_out, int out_size)
{
    const float* x      = (const float*)d_in[0];
    const float* W_qkv  = (const float*)d_in[1];
    const float* W_v    = (const float*)d_in[2];
    const float* W_proj = (const float*)d_in[3];
    const float* b_proj = (const float*)d_in[4];
    const float* mixl   = (const float*)d_in[5];
    float* out = (float*)d_out;

    float *pY, *pV, *pCtx, *pS4;
    __nv_bfloat16 *pVth, *pVtl;
    cudaGetSymbolAddress((void**)&pY,   g_Y);
    cudaGetSymbolAddress((void**)&pV,   g_V);
    cudaGetSymbolAddress((void**)&pCtx, g_ctx);
    cudaGetSymbolAddress((void**)&pS4,  g_S4);
    cudaGetSymbolAddress((void**)&pVth, g_Vth);
    cudaGetSymbolAddress((void**)&pVtl, g_Vtl);

    static bool attrDone = false;
    if (!attrDone) {
        cudaFuncSetAttribute(attn_kernel,
                             cudaFuncAttributeMaxDynamicSharedMemorySize, ATTN_SMEM);
        attrDone = true;
    }

    dim3 blk(256);

    // 1) Y = x @ W_qkv[0:512].T
    hmma_gemm<<<dim3(4, 64, 1), blk>>>(
        x, W_qkv, pY, nullptr, DIM, DIM, DIM, 512, 1.0f, 0, 0, 0, 0, 0, 1);

    // 2) V = x @ W_v.T
    hmma_gemm<<<dim3(6, 64, 1), blk>>>(
        x, W_v, pV, nullptr, DIM, DIM, DIM, DIM, 1.0f, 0, 0, 0, 0, 0, 1);

    // 2b) V -> per-head transposed bf16 hi/lo
    vconvert<<<dim3(16, 96, 1), blk>>>(pV, pVth, pVtl);

    // 3) S4 = 0.125 * q @ k.T
    hmma_gemm<<<dim3(8, 8, B_SZ * KG), blk>>>(
        pY, pY + 256, pS4, nullptr, HD, 512, 512, N_SEQ, 0.125f,
        (long)N_SEQ * 512, 64, (long)N_SEQ * 512, 64, (long)N_SEQ * N_SEQ, KG);

    // 4) attention (PV on tensor cores)
    attn_kernel<<<dim3(16, 6, 8), blk, ATTN_SMEM>>>(pS4, pVth, pVtl, mixl, pCtx);

    // 5) out = ctx @ W_proj.T + b_proj
    hmma_gemm<<<dim3(6, 64, 1), blk>>>(
        pCtx, W_proj, out, b_proj, DIM, DIM, DIM, DIM, 1.0f, 0, 0, 0, 0, 0, 1);
}